// round 8
// baseline (speedup 1.0000x reference)
#include <cuda_runtime.h>
#include <cuda_fp16.h>
#include <math.h>
#include <stdint.h>

#define DDIM 256
#define NROWS 8192
#define BM 256
#define BN 128
#define BK 64                     // fp16 per k-chunk
#define NITER (DDIM / BK)         // 4
#define ROWB 144                  // 128B data + 16B pad (conflict-free ldmatrix)
#define A_BYTES (BM * ROWB)       // 36864
#define STAGE_BYTES ((BM + BN) * ROWB)    // 55296
#define SMEM_TOTAL (NITER * STAGE_BYTES)  // 221184 (<= 227KB) -> 1 CTA/SM

// -------------------- scratch --------------------
__device__ __half g_Ah[NROWS * DDIM];   // x1 * sqrt(alpha), fp16
__device__ __half g_Bh[NROWS * DDIM];   // x2 * sqrt(alpha), fp16
__device__ float g_n1[NROWS];
__device__ float g_n2[NROWS];
__device__ float g_sa[DDIM];

// -------------------- helpers --------------------
__device__ __forceinline__ uint32_t smem_u32(const void* p) {
    uint32_t a;
    asm("{ .reg .u64 t; cvta.to.shared.u64 t, %1; cvt.u32.u64 %0, t; }" : "=r"(a) : "l"(p));
    return a;
}
__device__ __forceinline__ void cp_async16(uint32_t saddr, const void* g) {
    asm volatile("cp.async.cg.shared.global [%0], [%1], 16;" :: "r"(saddr), "l"(g));
}
__device__ __forceinline__ void ldmatrix_x4(uint32_t* r, uint32_t saddr) {
    asm volatile("ldmatrix.sync.aligned.m8n8.x4.shared.b16 {%0,%1,%2,%3}, [%4];"
                 : "=r"(r[0]), "=r"(r[1]), "=r"(r[2]), "=r"(r[3]) : "r"(saddr));
}
__device__ __forceinline__ void mma_f16(float* c, const uint32_t* a, const uint32_t* b) {
    asm("mma.sync.aligned.m16n8k16.row.col.f32.f16.f16.f32 "
        "{%0,%1,%2,%3}, {%4,%5,%6,%7}, {%8,%9}, {%0,%1,%2,%3};"
        : "+f"(c[0]), "+f"(c[1]), "+f"(c[2]), "+f"(c[3])
        : "r"(a[0]), "r"(a[1]), "r"(a[2]), "r"(a[3]), "r"(b[0]), "r"(b[1]));
}

// -------------------- prep --------------------
__global__ void prep_alpha_kernel(const float* __restrict__ alpha_raw) {
    __shared__ float sh[DDIM];
    int d = threadIdx.x;
    float t = alpha_raw[d] * alpha_raw[d];
    sh[d] = t;
    __syncthreads();
    #pragma unroll
    for (int s = 128; s > 0; s >>= 1) {
        if (d < s) sh[d] = fmaxf(sh[d], sh[d + s]);
        __syncthreads();
    }
    float mx = sh[0];
    __syncthreads();
    float e = expf(t - mx);
    sh[d] = e;
    __syncthreads();
    #pragma unroll
    for (int s = 128; s > 0; s >>= 1) {
        if (d < s) sh[d] += sh[d + s];
        __syncthreads();
    }
    g_sa[d] = sqrtf(e / sh[0]);
}

// one warp per row; rows [0,N) -> x1/Ah/n1, rows [N,N+M) -> x2/Bh/n2
__global__ void scale_kernel(const float* __restrict__ x1,
                             const float* __restrict__ x2,
                             __half* __restrict__ Ah,
                             __half* __restrict__ Bh,
                             float* __restrict__ n1,
                             float* __restrict__ n2,
                             int N) {
    const int w = (blockIdx.x * blockDim.x + threadIdx.x) >> 5;
    const int lane = threadIdx.x & 31;

    const float* src;
    __half* dst;
    if (w < N) { src = x1 + (size_t)w * DDIM; dst = Ah + (size_t)w * DDIM; }
    else       { src = x2 + (size_t)(w - N) * DDIM; dst = Bh + (size_t)(w - N) * DDIM; }

    float s = 0.0f;
    #pragma unroll
    for (int j = 0; j < 2; j++) {
        const int c = j * 128 + lane * 4;
        float4 xv = *(const float4*)(src + c);
        float4 sv = *(const float4*)(g_sa + c);
        float v0 = xv.x * sv.x, v1 = xv.y * sv.y, v2 = xv.z * sv.z, v3 = xv.w * sv.w;
        __half h[4] = { __float2half(v0), __float2half(v1),
                        __float2half(v2), __float2half(v3) };
        *(uint2*)(dst + c) = *(const uint2*)h;
        s += v0 * v0 + v1 * v1 + v2 * v2 + v3 * v3;
    }
    #pragma unroll
    for (int o = 16; o > 0; o >>= 1)
        s += __shfl_xor_sync(0xFFFFFFFFu, s, o);
    if (lane == 0) {
        if (w < N) n1[w] = s;
        else       n2[w - N] = s;
    }
}

// -------------------- fused HMMA GEMM + RBF epilogue --------------------
// 256 threads (8 warps, 4 in M x 2 in N), warp tile 64x64, CTA tile 256x128.
// All 4 K-chunks staged in smem up front (4 commit groups); no mid-loop fills.
__global__ void __launch_bounds__(256, 1)
rbf_mma_kernel(const __half* __restrict__ Ah,
               const __half* __restrict__ Bh,
               const float* __restrict__ n1,
               const float* __restrict__ n2,
               const float* __restrict__ variance_raw,
               float* __restrict__ out,
               int Mcols) {
    extern __shared__ char smem[];
    const uint32_t sbase = smem_u32(smem);
    const int tid = threadIdx.x;
    const int wid = tid >> 5;
    const int lane = tid & 31;
    const int wm = wid & 3;       // 4 warps in M, 64 rows each
    const int wn = wid >> 2;      // 2 warps in N, 64 cols each
    const int row0 = blockIdx.y * BM;
    const int col0 = blockIdx.x * BN;

    float acc[4][8][4];
    #pragma unroll
    for (int i = 0; i < 4; i++)
        #pragma unroll
        for (int j = 0; j < 8; j++)
            #pragma unroll
            for (int q = 0; q < 4; q++) acc[i][j][q] = 0.0f;

    // ---- load addressing: thread covers row r+32l, 16B-chunk c ----
    const int r = tid >> 3;            // [0,32)
    const int c = tid & 7;             // [0,8)
    const uint32_t soff0 = (uint32_t)(r * ROWB + c * 16);
    const __half* ag0 = Ah + (size_t)(row0 + r) * DDIM + c * 8;
    const __half* bg0 = Bh + (size_t)(col0 + r) * DDIM + c * 8;

    // prologue: stage ALL 4 K-chunks, one commit group each
    #pragma unroll
    for (int ck = 0; ck < NITER; ck++) {
        const int kk = ck * BK;
        const uint32_t ab = sbase + ck * STAGE_BYTES;
        const uint32_t bb = ab + A_BYTES;
        #pragma unroll
        for (int l = 0; l < 8; l++)          // A: 256 rows
            cp_async16(ab + soff0 + l * 32 * ROWB, ag0 + kk + (size_t)l * 32 * DDIM);
        #pragma unroll
        for (int l = 0; l < 4; l++)          // B: 128 rows
            cp_async16(bb + soff0 + l * 32 * ROWB, bg0 + kk + (size_t)l * 32 * DDIM);
        asm volatile("cp.async.commit_group;" ::: "memory");
    }

    // ---- hoisted ldmatrix within-stage offsets ----
    const int lrow = lane & 15;
    const uint32_t lkb = (uint32_t)((lane >> 4) * 16);
    uint32_t afoff[4], bfoff[4];
    #pragma unroll
    for (int mt = 0; mt < 4; mt++)
        afoff[mt] = (uint32_t)((wm * 64 + mt * 16 + lrow) * ROWB) + lkb;
    #pragma unroll
    for (int t = 0; t < 4; t++)
        bfoff[t] = (uint32_t)((wn * 64 + t * 16 + lrow) * ROWB) + lkb + A_BYTES;

    #pragma unroll
    for (int i = 0; i < NITER; i++) {
        if (i == 0)      asm volatile("cp.async.wait_group 3;" ::: "memory");
        else if (i == 1) asm volatile("cp.async.wait_group 2;" ::: "memory");
        else if (i == 2) asm volatile("cp.async.wait_group 1;" ::: "memory");
        else             asm volatile("cp.async.wait_group 0;" ::: "memory");
        __syncthreads();

        const uint32_t stb = sbase + i * STAGE_BYTES;

        #pragma unroll
        for (int ks = 0; ks < 4; ks++) {
            const uint32_t koff = stb + (uint32_t)(ks * 32);
            uint32_t af[4][4];
            #pragma unroll
            for (int mt = 0; mt < 4; mt++)
                ldmatrix_x4(af[mt], koff + afoff[mt]);
            uint32_t bf[8][2];
            #pragma unroll
            for (int t = 0; t < 4; t++) {
                uint32_t rr[4];
                ldmatrix_x4(rr, koff + bfoff[t]);
                bf[t * 2][0] = rr[0]; bf[t * 2][1] = rr[2];
                bf[t * 2 + 1][0] = rr[1]; bf[t * 2 + 1][1] = rr[3];
            }
            #pragma unroll
            for (int mt = 0; mt < 4; mt++)
                #pragma unroll
                for (int nt = 0; nt < 8; nt++)
                    mma_f16(acc[mt][nt], af[mt], bf[nt]);
        }
    }

    // -------- epilogue --------
    const float vr = variance_raw[0];
    const float var = vr * vr;
    const int qrow = lane >> 2;
    const int qcol = (lane & 3) * 2;

    #pragma unroll
    for (int mt = 0; mt < 4; mt++) {
        const int rg = row0 + wm * 64 + mt * 16 + qrow;
        const float rnA = n1[rg];
        const float rnB = n1[rg + 8];
        #pragma unroll
        for (int nt = 0; nt < 8; nt++) {
            const int cg = col0 + wn * 64 + nt * 8 + qcol;
            float2 nn = *(const float2*)(n2 + cg);
            float sq0 = fmaxf(fmaf(-2.0f, acc[mt][nt][0], rnA + nn.x), 0.0f);
            float sq1 = fmaxf(fmaf(-2.0f, acc[mt][nt][1], rnA + nn.y), 0.0f);
            float sq2 = fmaxf(fmaf(-2.0f, acc[mt][nt][2], rnB + nn.x), 0.0f);
            float sq3 = fmaxf(fmaf(-2.0f, acc[mt][nt][3], rnB + nn.y), 0.0f);
            float2 v0 = make_float2(var * __expf(-0.5f * sq0), var * __expf(-0.5f * sq1));
            float2 v1 = make_float2(var * __expf(-0.5f * sq2), var * __expf(-0.5f * sq3));
            *(float2*)(out + (size_t)rg * Mcols + cg) = v0;
            *(float2*)(out + (size_t)(rg + 8) * Mcols + cg) = v1;
        }
    }
}

// -------------------- launch --------------------
extern "C" void kernel_launch(void* const* d_in, const int* in_sizes, int n_in,
                              void* d_out, int out_size) {
    const float* x1 = (const float*)d_in[0];
    const float* x2 = (const float*)d_in[1];
    const float* alpha_raw = (const float*)d_in[2];
    const float* variance_raw = (const float*)d_in[3];
    float* out = (float*)d_out;

    int N = in_sizes[0] / DDIM;
    int M = in_sizes[1] / DDIM;

    __half *Ah, *Bh;
    float *n1, *n2;
    cudaGetSymbolAddress((void**)&Ah, g_Ah);
    cudaGetSymbolAddress((void**)&Bh, g_Bh);
    cudaGetSymbolAddress((void**)&n1, g_n1);
    cudaGetSymbolAddress((void**)&n2, g_n2);

    cudaFuncSetAttribute(rbf_mma_kernel, cudaFuncAttributeMaxDynamicSharedMemorySize, SMEM_TOTAL);

    prep_alpha_kernel<<<1, DDIM>>>(alpha_raw);
    scale_kernel<<<(N + M) / 8, 256>>>(x1, x2, Ah, Bh, n1, n2, N);

    dim3 grid(M / BN, N / BM);
    rbf_mma_kernel<<<grid, 256, SMEM_TOTAL>>>(Ah, Bh, n1, n2, variance_raw, out, M);
}

// round 9
// speedup vs baseline: 1.6500x; 1.6500x over previous
#include <cuda_runtime.h>
#include <cuda_fp16.h>
#include <math.h>
#include <stdint.h>

#define DDIM 256
#define NROWS 8192
#define BM 128
#define BN 128
#define BK 64                     // fp16 per k-chunk
#define NITER (DDIM / BK)         // 4
#define NSTAGE 3
#define ROWB 144                  // 128B data + 16B pad (conflict-free ldmatrix)
#define A_BYTES (BM * ROWB)       // 18432
#define STAGE_BYTES ((BM + BN) * ROWB)    // 36864
#define SMEM_TOTAL (NSTAGE * STAGE_BYTES) // 110592 -> 2 CTAs/SM

// -------------------- scratch --------------------
__device__ __half g_Ah[NROWS * DDIM];   // x1 * sqrt(alpha), fp16
__device__ __half g_Bh[NROWS * DDIM];   // x2 * sqrt(alpha), fp16
__device__ float g_n1[NROWS];
__device__ float g_n2[NROWS];
__device__ float g_sa[DDIM];

// -------------------- helpers --------------------
__device__ __forceinline__ uint32_t smem_u32(const void* p) {
    uint32_t a;
    asm("{ .reg .u64 t; cvta.to.shared.u64 t, %1; cvt.u32.u64 %0, t; }" : "=r"(a) : "l"(p));
    return a;
}
__device__ __forceinline__ void cp_async16(uint32_t saddr, const void* g) {
    asm volatile("cp.async.cg.shared.global [%0], [%1], 16;" :: "r"(saddr), "l"(g));
}
__device__ __forceinline__ void ldmatrix_x4(uint32_t* r, uint32_t saddr) {
    asm volatile("ldmatrix.sync.aligned.m8n8.x4.shared.b16 {%0,%1,%2,%3}, [%4];"
                 : "=r"(r[0]), "=r"(r[1]), "=r"(r[2]), "=r"(r[3]) : "r"(saddr));
}
__device__ __forceinline__ void mma_f16(float* c, const uint32_t* a, const uint32_t* b) {
    asm("mma.sync.aligned.m16n8k16.row.col.f32.f16.f16.f32 "
        "{%0,%1,%2,%3}, {%4,%5,%6,%7}, {%8,%9}, {%0,%1,%2,%3};"
        : "+f"(c[0]), "+f"(c[1]), "+f"(c[2]), "+f"(c[3])
        : "r"(a[0]), "r"(a[1]), "r"(a[2]), "r"(a[3]), "r"(b[0]), "r"(b[1]));
}

// -------------------- prep --------------------
__global__ void prep_alpha_kernel(const float* __restrict__ alpha_raw) {
    __shared__ float sh[DDIM];
    int d = threadIdx.x;
    float t = alpha_raw[d] * alpha_raw[d];
    sh[d] = t;
    __syncthreads();
    #pragma unroll
    for (int s = 128; s > 0; s >>= 1) {
        if (d < s) sh[d] = fmaxf(sh[d], sh[d + s]);
        __syncthreads();
    }
    float mx = sh[0];
    __syncthreads();
    float e = expf(t - mx);
    sh[d] = e;
    __syncthreads();
    #pragma unroll
    for (int s = 128; s > 0; s >>= 1) {
        if (d < s) sh[d] += sh[d + s];
        __syncthreads();
    }
    g_sa[d] = sqrtf(e / sh[0]);
}

// one warp per row; rows [0,N) -> x1/Ah/n1, rows [N,N+M) -> x2/Bh/n2
__global__ void scale_kernel(const float* __restrict__ x1,
                             const float* __restrict__ x2,
                             __half* __restrict__ Ah,
                             __half* __restrict__ Bh,
                             float* __restrict__ n1,
                             float* __restrict__ n2,
                             int N) {
    const int w = (blockIdx.x * blockDim.x + threadIdx.x) >> 5;
    const int lane = threadIdx.x & 31;

    const float* src;
    __half* dst;
    if (w < N) { src = x1 + (size_t)w * DDIM; dst = Ah + (size_t)w * DDIM; }
    else       { src = x2 + (size_t)(w - N) * DDIM; dst = Bh + (size_t)(w - N) * DDIM; }

    float s = 0.0f;
    #pragma unroll
    for (int j = 0; j < 2; j++) {
        const int c = j * 128 + lane * 4;
        float4 xv = *(const float4*)(src + c);
        float4 sv = *(const float4*)(g_sa + c);
        float v0 = xv.x * sv.x, v1 = xv.y * sv.y, v2 = xv.z * sv.z, v3 = xv.w * sv.w;
        __half h[4] = { __float2half(v0), __float2half(v1),
                        __float2half(v2), __float2half(v3) };
        *(uint2*)(dst + c) = *(const uint2*)h;
        s += v0 * v0 + v1 * v1 + v2 * v2 + v3 * v3;
    }
    #pragma unroll
    for (int o = 16; o > 0; o >>= 1)
        s += __shfl_xor_sync(0xFFFFFFFFu, s, o);
    if (lane == 0) {
        if (w < N) n1[w] = s;
        else       n2[w - N] = s;
    }
}

// -------------------- fused HMMA GEMM + RBF epilogue --------------------
// 128 threads (4 warps, 2x2), warp tile 64x64, CTA tile 128x128, K=256.
// Double-buffered fragment registers: LDSM for k-step ks+1 issues BEFORE the
// MMAs of k-step ks, so LDSM latency drains under tensor-pipe issue.
__global__ void __launch_bounds__(128, 2)
rbf_mma_kernel(const __half* __restrict__ Ah,
               const __half* __restrict__ Bh,
               const float* __restrict__ n1,
               const float* __restrict__ n2,
               const float* __restrict__ variance_raw,
               float* __restrict__ out,
               int Mcols) {
    extern __shared__ char smem[];
    const uint32_t sbase = smem_u32(smem);
    const int tid = threadIdx.x;
    const int wid = tid >> 5;
    const int lane = tid & 31;
    const int wm = wid & 1;       // 2 warps in M, 64 rows each
    const int wn = wid >> 1;      // 2 warps in N, 64 cols each
    const int row0 = blockIdx.y * BM;
    const int col0 = blockIdx.x * BN;

    float acc[4][8][4];
    #pragma unroll
    for (int i = 0; i < 4; i++)
        #pragma unroll
        for (int j = 0; j < 8; j++)
            #pragma unroll
            for (int q = 0; q < 4; q++) acc[i][j][q] = 0.0f;

    // ---- hoisted per-thread load state: 8 A-chunks + 8 B-chunks of 16B ----
    uint32_t coff[8];
    const __half *agp[8], *bgp[8];
    #pragma unroll
    for (int l = 0; l < 8; l++) {
        int u = tid + l * 128;
        int r = u >> 3, c = u & 7;
        coff[l] = (uint32_t)(r * ROWB + c * 16);
        agp[l] = Ah + (size_t)(row0 + r) * DDIM + c * 8;
        bgp[l] = Bh + (size_t)(col0 + r) * DDIM + c * 8;
    }

    auto fill = [&](int ck) {
        const int kk = ck * BK;
        const uint32_t ab = sbase + (ck % NSTAGE) * STAGE_BYTES;
        const uint32_t bb = ab + A_BYTES;
        #pragma unroll
        for (int l = 0; l < 8; l++)
            cp_async16(ab + coff[l], agp[l] + kk);
        #pragma unroll
        for (int l = 0; l < 8; l++)
            cp_async16(bb + coff[l], bgp[l] + kk);
        asm volatile("cp.async.commit_group;" ::: "memory");
    };

    // ---- hoisted ldmatrix within-stage offsets ----
    const int lrow = lane & 15;
    const uint32_t lkb = (uint32_t)((lane >> 4) * 16);
    uint32_t afoff[4], bfoff[4];
    #pragma unroll
    for (int mt = 0; mt < 4; mt++)
        afoff[mt] = (uint32_t)((wm * 64 + mt * 16 + lrow) * ROWB) + lkb;
    #pragma unroll
    for (int t = 0; t < 4; t++)
        bfoff[t] = (uint32_t)((wn * 64 + t * 16 + lrow) * ROWB) + lkb + A_BYTES;

    fill(0); fill(1);

    // double-buffered fragments
    uint32_t af[2][4][4], bf[2][8][2];

#define LOAD_FRAGS(buf, koff)                                                  \
    do {                                                                       \
        _Pragma("unroll")                                                      \
        for (int mt = 0; mt < 4; mt++)                                         \
            ldmatrix_x4(af[buf][mt], (koff) + afoff[mt]);                      \
        _Pragma("unroll")                                                      \
        for (int t = 0; t < 4; t++) {                                          \
            uint32_t rr[4];                                                    \
            ldmatrix_x4(rr, (koff) + bfoff[t]);                                \
            bf[buf][t * 2][0] = rr[0]; bf[buf][t * 2][1] = rr[2];              \
            bf[buf][t * 2 + 1][0] = rr[1]; bf[buf][t * 2 + 1][1] = rr[3];      \
        }                                                                      \
    } while (0)

    #pragma unroll
    for (int i = 0; i < NITER; i++) {
        if (i < NITER - 1) asm volatile("cp.async.wait_group 1;" ::: "memory");
        else               asm volatile("cp.async.wait_group 0;" ::: "memory");
        __syncthreads();

        if (i + 2 < NITER) fill(i + 2);

        const uint32_t stb = sbase + (i % NSTAGE) * STAGE_BYTES;

        LOAD_FRAGS(0, stb);
        #pragma unroll
        for (int ks = 0; ks < 4; ks++) {
            if (ks < 3) LOAD_FRAGS((ks + 1) & 1, stb + (uint32_t)((ks + 1) * 32));
            const int cb = ks & 1;
            #pragma unroll
            for (int mt = 0; mt < 4; mt++)
                #pragma unroll
                for (int nt = 0; nt < 8; nt++)
                    mma_f16(acc[mt][nt], af[cb][mt], bf[cb][nt]);
        }
    }

    // -------- epilogue --------
    const float vr = variance_raw[0];
    const float var = vr * vr;
    const int qrow = lane >> 2;
    const int qcol = (lane & 3) * 2;

    #pragma unroll
    for (int mt = 0; mt < 4; mt++) {
        const int rg = row0 + wm * 64 + mt * 16 + qrow;
        const float rnA = n1[rg];
        const float rnB = n1[rg + 8];
        #pragma unroll
        for (int nt = 0; nt < 8; nt++) {
            const int cg = col0 + wn * 64 + nt * 8 + qcol;
            float2 nn = *(const float2*)(n2 + cg);
            float sq0 = fmaxf(fmaf(-2.0f, acc[mt][nt][0], rnA + nn.x), 0.0f);
            float sq1 = fmaxf(fmaf(-2.0f, acc[mt][nt][1], rnA + nn.y), 0.0f);
            float sq2 = fmaxf(fmaf(-2.0f, acc[mt][nt][2], rnB + nn.x), 0.0f);
            float sq3 = fmaxf(fmaf(-2.0f, acc[mt][nt][3], rnB + nn.y), 0.0f);
            float2 v0 = make_float2(var * __expf(-0.5f * sq0), var * __expf(-0.5f * sq1));
            float2 v1 = make_float2(var * __expf(-0.5f * sq2), var * __expf(-0.5f * sq3));
            *(float2*)(out + (size_t)rg * Mcols + cg) = v0;
            *(float2*)(out + (size_t)(rg + 8) * Mcols + cg) = v1;
        }
    }
}

// -------------------- launch --------------------
extern "C" void kernel_launch(void* const* d_in, const int* in_sizes, int n_in,
                              void* d_out, int out_size) {
    const float* x1 = (const float*)d_in[0];
    const float* x2 = (const float*)d_in[1];
    const float* alpha_raw = (const float*)d_in[2];
    const float* variance_raw = (const float*)d_in[3];
    float* out = (float*)d_out;

    int N = in_sizes[0] / DDIM;
    int M = in_sizes[1] / DDIM;

    __half *Ah, *Bh;
    float *n1, *n2;
    cudaGetSymbolAddress((void**)&Ah, g_Ah);
    cudaGetSymbolAddress((void**)&Bh, g_Bh);
    cudaGetSymbolAddress((void**)&n1, g_n1);
    cudaGetSymbolAddress((void**)&n2, g_n2);

    cudaFuncSetAttribute(rbf_mma_kernel, cudaFuncAttributeMaxDynamicSharedMemorySize, SMEM_TOTAL);

    prep_alpha_kernel<<<1, DDIM>>>(alpha_raw);
    scale_kernel<<<(N + M) / 8, 256>>>(x1, x2, Ah, Bh, n1, n2, N);

    dim3 grid(M / BN, N / BM);
    rbf_mma_kernel<<<grid, 128, SMEM_TOTAL>>>(Ah, Bh, n1, n2, variance_raw, out, M);
}